// round 1
// baseline (speedup 1.0000x reference)
#include <cuda_runtime.h>

// Problem constants
#define HEADS 8
#define BATCH 8
#define SEQ   1024          // 32*32
#define HD    64
#define DMODEL 512
#define CIN   512
#define NB    (HEADS*BATCH) // 64 head-batches
#define HSTRIDE (BATCH*SEQ*HD) // 524288: stride between heads in split layout

// Scratch: Q,K,V in head-split layout [n][s][hd], n = head*BATCH + b
__device__ float g_Q[NB * SEQ * HD];
__device__ float g_K[NB * SEQ * HD];
__device__ float g_V[NB * SEQ * HD];

typedef unsigned long long u64;

__device__ __forceinline__ u64 pack2(float lo, float hi) {
    u64 r; asm("mov.b64 %0, {%1, %2};" : "=l"(r) : "f"(lo), "f"(hi)); return r;
}
__device__ __forceinline__ void unpack2(u64 v, float& lo, float& hi) {
    asm("mov.b64 {%0, %1}, %2;" : "=f"(lo), "=f"(hi) : "l"(v));
}
__device__ __forceinline__ u64 fma2(u64 a, u64 b, u64 c) {
    u64 d; asm("fma.rn.f32x2 %0, %1, %2, %3;" : "=l"(d) : "l"(a), "l"(b), "l"(c)); return d;
}
__device__ __forceinline__ u64 mul2(u64 a, u64 b) {
    u64 d; asm("mul.rn.f32x2 %0, %1, %2;" : "=l"(d) : "l"(a), "l"(b)); return d;
}

// ---------------------------------------------------------------------------
// Kernel A: fused Q/K/V projection GEMM.
// Y[m][d] = sum_c X[m][c] * W[c][d] + bias[d], written head-split:
// Out[(d>>6)*HSTRIDE + m*64 + (d&63)]   (m = b*SEQ + s)
// Block tile 128x128, K-chunk 16, 256 threads, 8x8 per thread (f32x2 packed).
// grid = (4, 64, 3), z selects q/k/v.
// ---------------------------------------------------------------------------
__global__ void __launch_bounds__(256) proj_kernel(
    const float* __restrict__ Xq, const float* __restrict__ Xk, const float* __restrict__ Xv,
    const float* __restrict__ Wq, const float* __restrict__ Wk, const float* __restrict__ Wv,
    const float* __restrict__ bq, const float* __restrict__ bk, const float* __restrict__ bv)
{
    __shared__ float As[16][132];   // transposed A tile [k][m], padded
    __shared__ float Bs[16][128];   // B tile [k][n]

    const int z = blockIdx.z;
    const float* __restrict__ X    = (z == 0) ? Xq : (z == 1) ? Xk : Xv;
    const float* __restrict__ W    = (z == 0) ? Wq : (z == 1) ? Wk : Wv;
    const float* __restrict__ bias = (z == 0) ? bq : (z == 1) ? bk : bv;
    float* __restrict__ Out        = (z == 0) ? g_Q : (z == 1) ? g_K : g_V;

    const int m0 = blockIdx.y * 128;
    const int n0 = blockIdx.x * 128;
    const int tid = threadIdx.x;
    const int tx = tid & 15;        // 0..15 -> col group
    const int ty = tid >> 4;        // 0..15 -> row group

    // A-load mapping: 4 threads per row, float4 along K
    const int rowA = tid >> 2;          // 0..63
    const int colA = (tid & 3) * 4;     // 0,4,8,12
    // B-load mapping: 16 threads per row, float4 along N
    const int rowB = tid >> 4;          // 0..15
    const int colB = (tid & 15) * 4;    // 0..60

    u64 acc[8][4];
    #pragma unroll
    for (int i = 0; i < 8; i++)
        #pragma unroll
        for (int j = 0; j < 4; j++) acc[i][j] = 0ull;

    for (int k0 = 0; k0 < CIN; k0 += 16) {
        float4 a0 = *(const float4*)&X[(size_t)(m0 + rowA) * CIN + k0 + colA];
        float4 a1 = *(const float4*)&X[(size_t)(m0 + 64 + rowA) * CIN + k0 + colA];
        float4 b0 = *(const float4*)&W[(size_t)(k0 + rowB) * DMODEL + n0 + colB];
        float4 b1 = *(const float4*)&W[(size_t)(k0 + rowB) * DMODEL + n0 + 64 + colB];

        __syncthreads();   // previous compute done before overwriting smem
        As[colA + 0][rowA] = a0.x; As[colA + 1][rowA] = a0.y;
        As[colA + 2][rowA] = a0.z; As[colA + 3][rowA] = a0.w;
        As[colA + 0][rowA + 64] = a1.x; As[colA + 1][rowA + 64] = a1.y;
        As[colA + 2][rowA + 64] = a1.z; As[colA + 3][rowA + 64] = a1.w;
        *(float4*)&Bs[rowB][colB]      = b0;
        *(float4*)&Bs[rowB][colB + 64] = b1;
        __syncthreads();

        #pragma unroll
        for (int kk = 0; kk < 16; kk++) {
            float4 av0 = *(const float4*)&As[kk][ty * 4];
            float4 av1 = *(const float4*)&As[kk][ty * 4 + 64];
            float4 bv0 = *(const float4*)&Bs[kk][tx * 4];
            float4 bv1 = *(const float4*)&Bs[kk][tx * 4 + 64];
            u64 bp[4];
            bp[0] = pack2(bv0.x, bv0.y); bp[1] = pack2(bv0.z, bv0.w);
            bp[2] = pack2(bv1.x, bv1.y); bp[3] = pack2(bv1.z, bv1.w);
            float ar[8] = {av0.x, av0.y, av0.z, av0.w, av1.x, av1.y, av1.z, av1.w};
            #pragma unroll
            for (int i = 0; i < 8; i++) {
                u64 ai = pack2(ar[i], ar[i]);
                #pragma unroll
                for (int j = 0; j < 4; j++)
                    acc[i][j] = fma2(ai, bp[j], acc[i][j]);
            }
        }
    }

    // Epilogue: head-split scatter (4-col groups never cross a 64-boundary)
    const int c0 = n0 + tx * 4;
    float4 bb0 = *(const float4*)&bias[c0];
    float4 bb1 = *(const float4*)&bias[c0 + 64];
    #pragma unroll
    for (int i = 0; i < 8; i++) {
        const int m = m0 + ((i < 4) ? (ty * 4 + i) : (64 + ty * 4 + (i - 4)));
        float x0, x1, x2, x3;

        unpack2(acc[i][0], x0, x1); unpack2(acc[i][1], x2, x3);
        float4 o0 = make_float4(x0 + bb0.x, x1 + bb0.y, x2 + bb0.z, x3 + bb0.w);
        int d = c0;
        *(float4*)&Out[(size_t)(d >> 6) * HSTRIDE + (size_t)m * 64 + (d & 63)] = o0;

        unpack2(acc[i][2], x0, x1); unpack2(acc[i][3], x2, x3);
        float4 o1 = make_float4(x0 + bb1.x, x1 + bb1.y, x2 + bb1.z, x3 + bb1.w);
        d = c0 + 64;
        *(float4*)&Out[(size_t)(d >> 6) * HSTRIDE + (size_t)m * 64 + (d & 63)] = o1;
    }
}

// ---------------------------------------------------------------------------
// Kernel B: flash attention, one query per thread.
// grid = (SEQ/128, NB), block = 128. K/V tiles of 64 staged via smem.
// Writes directly to d_out in (B,32,32,512) layout with head-major channels.
// ---------------------------------------------------------------------------
__global__ void __launch_bounds__(128) attn_kernel(float* __restrict__ out)
{
    __shared__ float Ks[64][64];
    __shared__ float Vs[64][64];

    const int n  = blockIdx.y;               // head*BATCH + b
    const int q  = blockIdx.x * 128 + threadIdx.x;
    const int tid = threadIdx.x;

    // q row, pre-scaled by 1/sqrt(64)
    u64 qp[32];
    {
        const float* qrow = &g_Q[((size_t)n * SEQ + q) * HD];
        #pragma unroll
        for (int i = 0; i < 16; i++) {
            float4 v = *(const float4*)&qrow[i * 4];
            qp[2 * i]     = pack2(v.x * 0.125f, v.y * 0.125f);
            qp[2 * i + 1] = pack2(v.z * 0.125f, v.w * 0.125f);
        }
    }

    u64 acc[32];
    #pragma unroll
    for (int i = 0; i < 32; i++) acc[i] = 0ull;
    float mrun = -1e30f, lrun = 0.0f;

    const float* Kbase = &g_K[(size_t)n * SEQ * HD];
    const float* Vbase = &g_V[(size_t)n * SEQ * HD];

    for (int k0 = 0; k0 < SEQ; k0 += 64) {
        __syncthreads();
        // cooperative, fully-coalesced 16KB tile loads (tiles are contiguous)
        #pragma unroll
        for (int i = 0; i < 8; i++) {
            int idx = tid * 4 + i * 512;
            *(float4*)&((float*)Ks)[idx] = *(const float4*)&Kbase[(size_t)k0 * HD + idx];
            *(float4*)&((float*)Vs)[idx] = *(const float4*)&Vbase[(size_t)k0 * HD + idx];
        }
        __syncthreads();

        #pragma unroll
        for (int c = 0; c < 64; c += 8) {
            float s[8];
            #pragma unroll
            for (int j = 0; j < 8; j++) {
                const ulonglong2* kr = (const ulonglong2*)&Ks[c + j][0];
                u64 sa = 0ull, sb = 0ull;
                #pragma unroll
                for (int d = 0; d < 16; d++) {
                    ulonglong2 kv = kr[d];           // LDS.128 broadcast
                    sa = fma2(qp[2 * d],     kv.x, sa);
                    sb = fma2(qp[2 * d + 1], kv.y, sb);
                }
                float a0, a1, b0, b1;
                unpack2(sa, a0, a1); unpack2(sb, b0, b1);
                s[j] = (a0 + a1) + (b0 + b1);
            }

            float mn = mrun;
            #pragma unroll
            for (int j = 0; j < 8; j++) mn = fmaxf(mn, s[j]);
            const float alpha = __expf(mrun - mn);
            mrun = mn;

            float p[8]; float ls = 0.0f;
            #pragma unroll
            for (int j = 0; j < 8; j++) { p[j] = __expf(s[j] - mn); ls += p[j]; }
            lrun = lrun * alpha + ls;

            const u64 al2 = pack2(alpha, alpha);
            #pragma unroll
            for (int d = 0; d < 32; d++) acc[d] = mul2(acc[d], al2);

            #pragma unroll
            for (int j = 0; j < 8; j++) {
                const u64 pj = pack2(p[j], p[j]);
                const ulonglong2* vr = (const ulonglong2*)&Vs[c + j][0];
                #pragma unroll
                for (int d = 0; d < 16; d++) {
                    ulonglong2 vv = vr[d];           // LDS.128 broadcast
                    acc[2 * d]     = fma2(pj, vv.x, acc[2 * d]);
                    acc[2 * d + 1] = fma2(pj, vv.y, acc[2 * d + 1]);
                }
            }
        }
    }

    // Epilogue: normalize and scatter to (B,S,heads*hd) with head-major channels
    const float inv = 1.0f / lrun;
    const int head = n >> 3, b = n & 7;
    float* orow = &out[((size_t)(b * SEQ + q)) * DMODEL + head * HD];
    #pragma unroll
    for (int i = 0; i < 16; i++) {
        float x0, x1, y0, y1;
        unpack2(acc[2 * i], x0, x1); unpack2(acc[2 * i + 1], y0, y1);
        float4 o = make_float4(x0 * inv, x1 * inv, y0 * inv, y1 * inv);
        *(float4*)&orow[i * 4] = o;
    }
}

extern "C" void kernel_launch(void* const* d_in, const int* in_sizes, int n_in,
                              void* d_out, int out_size)
{
    const float* q_in = (const float*)d_in[0];
    const float* k_in = (const float*)d_in[1];
    const float* v_in = (const float*)d_in[2];
    const float* Wq   = (const float*)d_in[3];
    const float* bq   = (const float*)d_in[4];
    const float* Wk   = (const float*)d_in[5];
    const float* bk   = (const float*)d_in[6];
    const float* Wv   = (const float*)d_in[7];
    const float* bv   = (const float*)d_in[8];
    float* out = (float*)d_out;

    dim3 gp(DMODEL / 128, (BATCH * SEQ) / 128, 3);   // (4, 64, 3)
    proj_kernel<<<gp, 256>>>(q_in, k_in, v_in, Wq, Wk, Wv, bq, bk, bv);

    dim3 ga(SEQ / 128, NB);                          // (8, 64)
    attn_kernel<<<ga, 128>>>(out);
}

// round 2
// speedup vs baseline: 1.0922x; 1.0922x over previous
#include <cuda_runtime.h>

// Problem constants
#define HEADS 8
#define BATCH 8
#define SEQ   1024          // 32*32
#define HD    64
#define DMODEL 512
#define CIN   512
#define NB    (HEADS*BATCH) // 64 head-batches
#define HSTRIDE (BATCH*SEQ*HD) // 524288: stride between heads in split layout

// Scratch: Q,K,V in head-split layout [n][s][hd], n = head*BATCH + b
__device__ float g_Q[NB * SEQ * HD];
__device__ float g_K[NB * SEQ * HD];
__device__ float g_V[NB * SEQ * HD];

typedef unsigned long long u64;

__device__ __forceinline__ u64 pack2(float lo, float hi) {
    u64 r; asm("mov.b64 %0, {%1, %2};" : "=l"(r) : "f"(lo), "f"(hi)); return r;
}
__device__ __forceinline__ void unpack2(u64 v, float& lo, float& hi) {
    asm("mov.b64 {%0, %1}, %2;" : "=f"(lo), "=f"(hi) : "l"(v));
}
__device__ __forceinline__ u64 fma2(u64 a, u64 b, u64 c) {
    u64 d; asm("fma.rn.f32x2 %0, %1, %2, %3;" : "=l"(d) : "l"(a), "l"(b), "l"(c)); return d;
}
__device__ __forceinline__ u64 mul2(u64 a, u64 b) {
    u64 d; asm("mul.rn.f32x2 %0, %1, %2;" : "=l"(d) : "l"(a), "l"(b)); return d;
}

// ---------------------------------------------------------------------------
// Kernel A: fused Q/K/V projection GEMM (unchanged from R1; ~66% of fp32x2 SOL).
// ---------------------------------------------------------------------------
__global__ void __launch_bounds__(256) proj_kernel(
    const float* __restrict__ Xq, const float* __restrict__ Xk, const float* __restrict__ Xv,
    const float* __restrict__ Wq, const float* __restrict__ Wk, const float* __restrict__ Wv,
    const float* __restrict__ bq, const float* __restrict__ bk, const float* __restrict__ bv)
{
    __shared__ float As[16][132];   // transposed A tile [k][m], padded
    __shared__ float Bs[16][128];   // B tile [k][n]

    const int z = blockIdx.z;
    const float* __restrict__ X    = (z == 0) ? Xq : (z == 1) ? Xk : Xv;
    const float* __restrict__ W    = (z == 0) ? Wq : (z == 1) ? Wk : Wv;
    const float* __restrict__ bias = (z == 0) ? bq : (z == 1) ? bk : bv;
    float* __restrict__ Out        = (z == 0) ? g_Q : (z == 1) ? g_K : g_V;

    const int m0 = blockIdx.y * 128;
    const int n0 = blockIdx.x * 128;
    const int tid = threadIdx.x;
    const int tx = tid & 15;
    const int ty = tid >> 4;

    const int rowA = tid >> 2;
    const int colA = (tid & 3) * 4;
    const int rowB = tid >> 4;
    const int colB = (tid & 15) * 4;

    u64 acc[8][4];
    #pragma unroll
    for (int i = 0; i < 8; i++)
        #pragma unroll
        for (int j = 0; j < 4; j++) acc[i][j] = 0ull;

    for (int k0 = 0; k0 < CIN; k0 += 16) {
        float4 a0 = *(const float4*)&X[(size_t)(m0 + rowA) * CIN + k0 + colA];
        float4 a1 = *(const float4*)&X[(size_t)(m0 + 64 + rowA) * CIN + k0 + colA];
        float4 b0 = *(const float4*)&W[(size_t)(k0 + rowB) * DMODEL + n0 + colB];
        float4 b1 = *(const float4*)&W[(size_t)(k0 + rowB) * DMODEL + n0 + 64 + colB];

        __syncthreads();
        As[colA + 0][rowA] = a0.x; As[colA + 1][rowA] = a0.y;
        As[colA + 2][rowA] = a0.z; As[colA + 3][rowA] = a0.w;
        As[colA + 0][rowA + 64] = a1.x; As[colA + 1][rowA + 64] = a1.y;
        As[colA + 2][rowA + 64] = a1.z; As[colA + 3][rowA + 64] = a1.w;
        *(float4*)&Bs[rowB][colB]      = b0;
        *(float4*)&Bs[rowB][colB + 64] = b1;
        __syncthreads();

        #pragma unroll
        for (int kk = 0; kk < 16; kk++) {
            float4 av0 = *(const float4*)&As[kk][ty * 4];
            float4 av1 = *(const float4*)&As[kk][ty * 4 + 64];
            float4 bv0 = *(const float4*)&Bs[kk][tx * 4];
            float4 bv1 = *(const float4*)&Bs[kk][tx * 4 + 64];
            u64 bp[4];
            bp[0] = pack2(bv0.x, bv0.y); bp[1] = pack2(bv0.z, bv0.w);
            bp[2] = pack2(bv1.x, bv1.y); bp[3] = pack2(bv1.z, bv1.w);
            float ar[8] = {av0.x, av0.y, av0.z, av0.w, av1.x, av1.y, av1.z, av1.w};
            #pragma unroll
            for (int i = 0; i < 8; i++) {
                u64 ai = pack2(ar[i], ar[i]);
                #pragma unroll
                for (int j = 0; j < 4; j++)
                    acc[i][j] = fma2(ai, bp[j], acc[i][j]);
            }
        }
    }

    const int c0 = n0 + tx * 4;
    float4 bb0 = *(const float4*)&bias[c0];
    float4 bb1 = *(const float4*)&bias[c0 + 64];
    #pragma unroll
    for (int i = 0; i < 8; i++) {
        const int m = m0 + ((i < 4) ? (ty * 4 + i) : (64 + ty * 4 + (i - 4)));
        float x0, x1, x2, x3;

        unpack2(acc[i][0], x0, x1); unpack2(acc[i][1], x2, x3);
        float4 o0 = make_float4(x0 + bb0.x, x1 + bb0.y, x2 + bb0.z, x3 + bb0.w);
        int d = c0;
        *(float4*)&Out[(size_t)(d >> 6) * HSTRIDE + (size_t)m * 64 + (d & 63)] = o0;

        unpack2(acc[i][2], x0, x1); unpack2(acc[i][3], x2, x3);
        float4 o1 = make_float4(x0 + bb1.x, x1 + bb1.y, x2 + bb1.z, x3 + bb1.w);
        d = c0 + 64;
        *(float4*)&Out[(size_t)(d >> 6) * HSTRIDE + (size_t)m * 64 + (d & 63)] = o1;
    }
}

// ---------------------------------------------------------------------------
// Kernel B: flash attention, restructured.
// 2 threads per query (partner lanes l / l+16 own head-dim halves, score
// combined by shfl_xor 16), 2 queries per thread -> each smem LDS.128 feeds
// 4 packed FMAs. __launch_bounds__(128,3) for 12 warps/SM.
// grid = (SEQ/128, NB), block = 128.
// ---------------------------------------------------------------------------
__global__ void __launch_bounds__(128, 3) attn_kernel(float* __restrict__ out)
{
    __shared__ float Ks[64][64];
    __shared__ float Vs[64][64];

    const int n    = blockIdx.y;               // head*BATCH + b
    const int tid  = threadIdx.x;
    const int lane = tid & 31;
    const int warp = tid >> 5;
    const int d0   = (lane >> 4) << 5;         // 0 or 32: this thread's dim half
    const int qbase = blockIdx.x * 128 + warp * 32;
    const int qa = qbase + (lane & 15);
    const int qb = qa + 16;

    // Load my half of the two query rows, pre-scaled by 1/sqrt(64)
    u64 qp_a[16], qp_b[16];
    {
        const float* ra = &g_Q[((size_t)n * SEQ + qa) * HD + d0];
        const float* rb = &g_Q[((size_t)n * SEQ + qb) * HD + d0];
        #pragma unroll
        for (int i = 0; i < 8; i++) {
            float4 va = *(const float4*)&ra[i * 4];
            float4 vb = *(const float4*)&rb[i * 4];
            qp_a[2 * i]     = pack2(va.x * 0.125f, va.y * 0.125f);
            qp_a[2 * i + 1] = pack2(va.z * 0.125f, va.w * 0.125f);
            qp_b[2 * i]     = pack2(vb.x * 0.125f, vb.y * 0.125f);
            qp_b[2 * i + 1] = pack2(vb.z * 0.125f, vb.w * 0.125f);
        }
    }

    u64 acc_a[16], acc_b[16];
    #pragma unroll
    for (int i = 0; i < 16; i++) { acc_a[i] = 0ull; acc_b[i] = 0ull; }
    float ma = -1e30f, mb = -1e30f, la = 0.0f, lb = 0.0f;

    const float* Kbase = &g_K[(size_t)n * SEQ * HD];
    const float* Vbase = &g_V[(size_t)n * SEQ * HD];

    for (int k0 = 0; k0 < SEQ; k0 += 64) {
        __syncthreads();
        #pragma unroll
        for (int i = 0; i < 8; i++) {
            int idx = tid * 4 + i * 512;
            *(float4*)&((float*)Ks)[idx] = *(const float4*)&Kbase[(size_t)k0 * HD + idx];
            *(float4*)&((float*)Vs)[idx] = *(const float4*)&Vbase[(size_t)k0 * HD + idx];
        }
        __syncthreads();

        for (int c = 0; c < 64; c += 4) {
            // ---- scores for 4 keys x 2 queries ----
            float s_a[4], s_b[4];
            #pragma unroll
            for (int j = 0; j < 4; j++) {
                const ulonglong2* kr = (const ulonglong2*)&Ks[c + j][d0];
                u64 a0 = 0ull, a1 = 0ull, b0 = 0ull, b1 = 0ull;
                #pragma unroll
                for (int d = 0; d < 8; d++) {
                    ulonglong2 kv = kr[d];            // 1 LDS.128 -> 4 fma2
                    a0 = fma2(qp_a[2 * d],     kv.x, a0);
                    a1 = fma2(qp_a[2 * d + 1], kv.y, a1);
                    b0 = fma2(qp_b[2 * d],     kv.x, b0);
                    b1 = fma2(qp_b[2 * d + 1], kv.y, b1);
                }
                float x0, x1, y0, y1;
                unpack2(a0, x0, x1); unpack2(a1, y0, y1);
                float pa = (x0 + x1) + (y0 + y1);
                unpack2(b0, x0, x1); unpack2(b1, y0, y1);
                float pb = (x0 + x1) + (y0 + y1);
                s_a[j] = pa + __shfl_xor_sync(0xffffffffu, pa, 16);
                s_b[j] = pb + __shfl_xor_sync(0xffffffffu, pb, 16);
            }

            // ---- online softmax update (both partner lanes compute identically) ----
            float mna = ma, mnb = mb;
            #pragma unroll
            for (int j = 0; j < 4; j++) { mna = fmaxf(mna, s_a[j]); mnb = fmaxf(mnb, s_b[j]); }
            const float alpha_a = __expf(ma - mna); ma = mna;
            const float alpha_b = __expf(mb - mnb); mb = mnb;
            float p_a[4], p_b[4], lsa = 0.0f, lsb = 0.0f;
            #pragma unroll
            for (int j = 0; j < 4; j++) {
                p_a[j] = __expf(s_a[j] - ma); lsa += p_a[j];
                p_b[j] = __expf(s_b[j] - mb); lsb += p_b[j];
            }
            la = la * alpha_a + lsa;
            lb = lb * alpha_b + lsb;

            const u64 aa = pack2(alpha_a, alpha_a);
            const u64 ab = pack2(alpha_b, alpha_b);
            #pragma unroll
            for (int d = 0; d < 16; d++) {
                acc_a[d] = mul2(acc_a[d], aa);
                acc_b[d] = mul2(acc_b[d], ab);
            }

            // ---- V accumulation: 1 LDS.128 -> 4 fma2 ----
            #pragma unroll
            for (int j = 0; j < 4; j++) {
                const ulonglong2* vr = (const ulonglong2*)&Vs[c + j][d0];
                const u64 pja = pack2(p_a[j], p_a[j]);
                const u64 pjb = pack2(p_b[j], p_b[j]);
                #pragma unroll
                for (int d = 0; d < 8; d++) {
                    ulonglong2 vv = vr[d];
                    acc_a[2 * d]     = fma2(pja, vv.x, acc_a[2 * d]);
                    acc_a[2 * d + 1] = fma2(pja, vv.y, acc_a[2 * d + 1]);
                    acc_b[2 * d]     = fma2(pjb, vv.x, acc_b[2 * d]);
                    acc_b[2 * d + 1] = fma2(pjb, vv.y, acc_b[2 * d + 1]);
                }
            }
        }
    }

    // Epilogue: normalize and scatter (head-major channel concat)
    const float inva = 1.0f / la;
    const float invb = 1.0f / lb;
    const int head = n >> 3, b = n & 7;
    float* rowa = &out[((size_t)(b * SEQ + qa)) * DMODEL + head * HD + d0];
    float* rowb = &out[((size_t)(b * SEQ + qb)) * DMODEL + head * HD + d0];
    #pragma unroll
    for (int i = 0; i < 8; i++) {
        float x0, x1, y0, y1;
        unpack2(acc_a[2 * i], x0, x1); unpack2(acc_a[2 * i + 1], y0, y1);
        *(float4*)&rowa[i * 4] = make_float4(x0 * inva, x1 * inva, y0 * inva, y1 * inva);
        unpack2(acc_b[2 * i], x0, x1); unpack2(acc_b[2 * i + 1], y0, y1);
        *(float4*)&rowb[i * 4] = make_float4(x0 * invb, x1 * invb, y0 * invb, y1 * invb);
    }
}

extern "C" void kernel_launch(void* const* d_in, const int* in_sizes, int n_in,
                              void* d_out, int out_size)
{
    const float* q_in = (const float*)d_in[0];
    const float* k_in = (const float*)d_in[1];
    const float* v_in = (const float*)d_in[2];
    const float* Wq   = (const float*)d_in[3];
    const float* bq   = (const float*)d_in[4];
    const float* Wk   = (const float*)d_in[5];
    const float* bk   = (const float*)d_in[6];
    const float* Wv   = (const float*)d_in[7];
    const float* bv   = (const float*)d_in[8];
    float* out = (float*)d_out;

    dim3 gp(DMODEL / 128, (BATCH * SEQ) / 128, 3);   // (4, 64, 3)
    proj_kernel<<<gp, 256>>>(q_in, k_in, v_in, Wq, Wk, Wv, bq, bk, bv);

    dim3 ga(SEQ / 128, NB);                          // (8, 64)
    attn_kernel<<<ga, 128>>>(out);
}

// round 3
// speedup vs baseline: 2.8996x; 2.6548x over previous
#include <cuda_runtime.h>
#include <cstdint>

// Problem constants
#define HEADS 8
#define BATCH 8
#define SEQ   1024          // 32*32
#define HD    64
#define DMODEL 512
#define CIN   512
#define NB    (HEADS*BATCH) // 64 head-batches
#define HSTRIDE (BATCH*SEQ*HD) // 524288

// Scratch: Q,K,V in head-split layout [n][s][hd], n = head*BATCH + b
__device__ float g_Q[NB * SEQ * HD];
__device__ float g_K[NB * SEQ * HD];
__device__ float g_V[NB * SEQ * HD];

// ---- helpers -------------------------------------------------------------
__device__ __forceinline__ uint32_t tf32bits(float x) {
    uint32_t u; asm("cvt.rna.tf32.f32 %0, %1;" : "=r"(u) : "f"(x)); return u;
}
__device__ __forceinline__ float tf32f(float x) {
    return __uint_as_float(tf32bits(x));
}
__device__ __forceinline__ float ex2(float x) {
    float r; asm("ex2.approx.ftz.f32 %0, %1;" : "=f"(r) : "f"(x)); return r;
}
// D += A(16x8) * B(8x8), tf32 inputs, fp32 accum
__device__ __forceinline__ void mma8(float* d, const uint32_t* a, uint32_t b0, uint32_t b1) {
    asm volatile(
        "mma.sync.aligned.m16n8k8.row.col.f32.tf32.tf32.f32 "
        "{%0,%1,%2,%3}, {%4,%5,%6,%7}, {%8,%9}, {%0,%1,%2,%3};\n"
        : "+f"(d[0]), "+f"(d[1]), "+f"(d[2]), "+f"(d[3])
        : "r"(a[0]), "r"(a[1]), "r"(a[2]), "r"(a[3]), "r"(b0), "r"(b1));
}
__device__ __forceinline__ uint32_t fbits(float x) { return __float_as_uint(x); }

// ---------------------------------------------------------------------------
// Kernel A: fused Q/K/V projection GEMM, tf32 MMA.
// Block 128x128 tile, 128 threads = 4 warps, warp tile 64x64 (mt=4, nt=8).
// A smem [m][k] stride 36 ; B smem [k][n] stride 136 (both conflict-free).
// grid = (4, 64, 3); z selects q/k/v. Head-split scatter on store.
// ---------------------------------------------------------------------------
#define ASTR 36
#define BSTR 136
__global__ void __launch_bounds__(128, 2) proj_kernel(
    const float* __restrict__ Xq, const float* __restrict__ Xk, const float* __restrict__ Xv,
    const float* __restrict__ Wq, const float* __restrict__ Wk, const float* __restrict__ Wv,
    const float* __restrict__ bq, const float* __restrict__ bk, const float* __restrict__ bv)
{
    __shared__ float As[128 * ASTR];
    __shared__ float Bs[32 * BSTR];

    const int z = blockIdx.z;
    const float* __restrict__ X    = (z == 0) ? Xq : (z == 1) ? Xk : Xv;
    const float* __restrict__ W    = (z == 0) ? Wq : (z == 1) ? Wk : Wv;
    const float* __restrict__ bias = (z == 0) ? bq : (z == 1) ? bk : bv;
    float* __restrict__ Out        = (z == 0) ? g_Q : (z == 1) ? g_K : g_V;

    const int m0 = blockIdx.y * 128;
    const int n0 = blockIdx.x * 128;
    const int tid = threadIdx.x;
    const int lane = tid & 31, warp = tid >> 5;
    const int wm = (warp & 1) * 64;
    const int wn = (warp >> 1) * 64;

    float c[4][8][4];
    #pragma unroll
    for (int mt = 0; mt < 4; mt++)
        #pragma unroll
        for (int nt = 0; nt < 8; nt++)
            #pragma unroll
            for (int i = 0; i < 4; i++) c[mt][nt][i] = 0.0f;

    for (int k0 = 0; k0 < CIN; k0 += 32) {
        __syncthreads();
        // A tile: row = tid, 8 float4 across k-chunk
        {
            const float* src = X + (size_t)(m0 + tid) * CIN + k0;
            float* dst = As + tid * ASTR;
            #pragma unroll
            for (int j = 0; j < 8; j++) {
                float4 v = *(const float4*)(src + 4 * j);
                float4 w4 = make_float4(tf32f(v.x), tf32f(v.y), tf32f(v.z), tf32f(v.w));
                *(float4*)(dst + 4 * j) = w4;
            }
        }
        // B tile: row = tid>>2, cols (tid&3)*4 + 16j
        {
            const float* src = W + (size_t)(k0 + (tid >> 2)) * DMODEL + n0 + (tid & 3) * 4;
            float* dst = Bs + (tid >> 2) * BSTR + (tid & 3) * 4;
            #pragma unroll
            for (int j = 0; j < 8; j++) {
                float4 v = *(const float4*)(src + 16 * j);
                float4 w4 = make_float4(tf32f(v.x), tf32f(v.y), tf32f(v.z), tf32f(v.w));
                *(float4*)(dst + 16 * j) = w4;
            }
        }
        __syncthreads();

        #pragma unroll
        for (int ks = 0; ks < 4; ks++) {
            uint32_t A[4][4];
            #pragma unroll
            for (int mt = 0; mt < 4; mt++) {
                const float* ap = As + (wm + mt * 16 + (lane >> 2)) * ASTR + 8 * ks + (lane & 3);
                A[mt][0] = fbits(ap[0]);
                A[mt][2] = fbits(ap[4]);
                A[mt][1] = fbits(ap[8 * ASTR]);
                A[mt][3] = fbits(ap[8 * ASTR + 4]);
            }
            #pragma unroll
            for (int nt = 0; nt < 8; nt++) {
                uint32_t b0 = fbits(Bs[(8 * ks + (lane & 3)) * BSTR + wn + 8 * nt + (lane >> 2)]);
                uint32_t b1 = fbits(Bs[(8 * ks + 4 + (lane & 3)) * BSTR + wn + 8 * nt + (lane >> 2)]);
                #pragma unroll
                for (int mt = 0; mt < 4; mt++) mma8(c[mt][nt], A[mt], b0, b1);
            }
        }
    }

    // Epilogue: bias + head-split scatter (pairs stay inside one 64-col group)
    #pragma unroll
    for (int mt = 0; mt < 4; mt++) {
        #pragma unroll
        for (int nt = 0; nt < 8; nt++) {
            const int d = n0 + wn + 8 * nt + 2 * (lane & 3);
            const float2 bb = *(const float2*)&bias[d];
            #pragma unroll
            for (int rh = 0; rh < 2; rh++) {
                const int m = m0 + wm + 16 * mt + (lane >> 2) + 8 * rh;
                float2 v = make_float2(c[mt][nt][2 * rh] + bb.x, c[mt][nt][2 * rh + 1] + bb.y);
                *(float2*)&Out[(size_t)(d >> 6) * HSTRIDE + (size_t)m * 64 + (d & 63)] = v;
            }
        }
    }
}

// ---------------------------------------------------------------------------
// Kernel B: flash attention with tf32 MMA.
// Block = 128 threads (4 warps), 128 queries; warp owns 32 queries (mt=2).
// KV tiles of 64. Q/K/V staged in smem (strides 68/68/72, conflict-free).
// Online softmax on C-fragments; P->A fragments via shfl (no smem trip).
// grid = (8, 64). Dynamic smem 70656 B.
// ---------------------------------------------------------------------------
#define QSTR 68
#define KSTR 68
#define VSTR 72
#define QSCALE (0.125f * 1.4426950408889634f)   // 1/sqrt(64) * log2(e)

__global__ void __launch_bounds__(128, 2) attn_kernel(float* __restrict__ out)
{
    extern __shared__ float sm[];
    float* Qs = sm;                       // [128][QSTR]
    float* Ks = Qs + 128 * QSTR;          // [64][KSTR]
    float* Vs = Ks + 64 * KSTR;           // [64][VSTR]

    const int n = blockIdx.y;             // head*BATCH + b
    const int tid = threadIdx.x;
    const int lane = tid & 31, warp = tid >> 5;
    const int q0 = blockIdx.x * 128;

    const float* Qg = g_Q + ((size_t)n * SEQ + q0) * HD;
    const float* Kg = g_K + (size_t)n * SEQ * HD;
    const float* Vg = g_V + (size_t)n * SEQ * HD;

    // Stage Q tile (scaled + tf32-rounded): row = tid
    {
        const float* src = Qg + (size_t)tid * HD;
        float* dst = Qs + tid * QSTR;
        #pragma unroll
        for (int j = 0; j < 16; j++) {
            float4 v = *(const float4*)(src + 4 * j);
            float4 w4 = make_float4(tf32f(v.x * QSCALE), tf32f(v.y * QSCALE),
                                    tf32f(v.z * QSCALE), tf32f(v.w * QSCALE));
            *(float4*)(dst + 4 * j) = w4;
        }
    }

    float o[2][8][4];
    #pragma unroll
    for (int mt = 0; mt < 2; mt++)
        #pragma unroll
        for (int nt = 0; nt < 8; nt++)
            #pragma unroll
            for (int i = 0; i < 4; i++) o[mt][nt][i] = 0.0f;
    float mrow[4] = {-1e30f, -1e30f, -1e30f, -1e30f};
    float lrow[4] = {0.0f, 0.0f, 0.0f, 0.0f};

    const int krow = tid & 63;
    const int kcb  = (tid >> 6) * 32;

    for (int kv = 0; kv < SEQ; kv += 64) {
        __syncthreads();
        // Stage K/V tiles (tf32-rounded)
        {
            const float* ksrc = Kg + (size_t)(kv + krow) * HD + kcb;
            const float* vsrc = Vg + (size_t)(kv + krow) * HD + kcb;
            float* kdst = Ks + krow * KSTR + kcb;
            float* vdst = Vs + krow * VSTR + kcb;
            #pragma unroll
            for (int j = 0; j < 8; j++) {
                float4 a = *(const float4*)(ksrc + 4 * j);
                *(float4*)(kdst + 4 * j) =
                    make_float4(tf32f(a.x), tf32f(a.y), tf32f(a.z), tf32f(a.w));
                float4 b = *(const float4*)(vsrc + 4 * j);
                *(float4*)(vdst + 4 * j) =
                    make_float4(tf32f(b.x), tf32f(b.y), tf32f(b.z), tf32f(b.w));
            }
        }
        __syncthreads();

        // ---- S = Q * K^T ----
        float s[2][8][4];
        #pragma unroll
        for (int mt = 0; mt < 2; mt++)
            #pragma unroll
            for (int nt = 0; nt < 8; nt++)
                #pragma unroll
                for (int i = 0; i < 4; i++) s[mt][nt][i] = 0.0f;

        #pragma unroll
        for (int ks = 0; ks < 8; ks++) {
            uint32_t A[2][4];
            #pragma unroll
            for (int mt = 0; mt < 2; mt++) {
                const float* qp = Qs + (warp * 32 + mt * 16 + (lane >> 2)) * QSTR + 8 * ks + (lane & 3);
                A[mt][0] = fbits(qp[0]);
                A[mt][2] = fbits(qp[4]);
                A[mt][1] = fbits(qp[8 * QSTR]);
                A[mt][3] = fbits(qp[8 * QSTR + 4]);
            }
            #pragma unroll
            for (int nt = 0; nt < 8; nt++) {
                uint32_t b0 = fbits(Ks[(8 * nt + (lane >> 2)) * KSTR + 8 * ks + (lane & 3)]);
                uint32_t b1 = fbits(Ks[(8 * nt + (lane >> 2)) * KSTR + 8 * ks + 4 + (lane & 3)]);
                mma8(s[0][nt], A[0], b0, b1);
                mma8(s[1][nt], A[1], b0, b1);
            }
        }

        // ---- online softmax on fragments ----
        #pragma unroll
        for (int slot = 0; slot < 4; slot++) {
            const int mt = slot >> 1, cb = (slot & 1) * 2;
            float mx = s[mt][0][cb];
            #pragma unroll
            for (int nt = 0; nt < 8; nt++) {
                mx = fmaxf(mx, s[mt][nt][cb]);
                mx = fmaxf(mx, s[mt][nt][cb + 1]);
            }
            mx = fmaxf(mx, __shfl_xor_sync(0xffffffffu, mx, 1));
            mx = fmaxf(mx, __shfl_xor_sync(0xffffffffu, mx, 2));
            const float mnew = fmaxf(mrow[slot], mx);
            const float alpha = ex2(mrow[slot] - mnew);
            mrow[slot] = mnew;
            float sum = 0.0f;
            #pragma unroll
            for (int nt = 0; nt < 8; nt++) {
                float p0 = ex2(s[mt][nt][cb] - mnew);
                float p1 = ex2(s[mt][nt][cb + 1] - mnew);
                s[mt][nt][cb] = p0; s[mt][nt][cb + 1] = p1;
                sum += p0 + p1;
            }
            sum += __shfl_xor_sync(0xffffffffu, sum, 1);
            sum += __shfl_xor_sync(0xffffffffu, sum, 2);
            lrow[slot] = lrow[slot] * alpha + sum;
            #pragma unroll
            for (int nt = 0; nt < 8; nt++) {
                o[mt][nt][cb]     *= alpha;
                o[mt][nt][cb + 1] *= alpha;
            }
        }

        // ---- O += P * V ----
        const int src0 = (lane & ~3) | ((lane >> 1) & 1);
        const int src2 = src0 | 2;
        const bool oddl = (lane & 1);
        #pragma unroll
        for (int kt = 0; kt < 8; kt++) {
            uint32_t A[2][4];
            #pragma unroll
            for (int mt = 0; mt < 2; mt++) {
                float v0 = __shfl_sync(0xffffffffu, s[mt][kt][0], src0);
                float v1 = __shfl_sync(0xffffffffu, s[mt][kt][1], src0);
                float w0 = __shfl_sync(0xffffffffu, s[mt][kt][0], src2);
                float w1 = __shfl_sync(0xffffffffu, s[mt][kt][1], src2);
                A[mt][0] = tf32bits(oddl ? v1 : v0);
                A[mt][2] = tf32bits(oddl ? w1 : w0);
                v0 = __shfl_sync(0xffffffffu, s[mt][kt][2], src0);
                v1 = __shfl_sync(0xffffffffu, s[mt][kt][3], src0);
                w0 = __shfl_sync(0xffffffffu, s[mt][kt][2], src2);
                w1 = __shfl_sync(0xffffffffu, s[mt][kt][3], src2);
                A[mt][1] = tf32bits(oddl ? v1 : v0);
                A[mt][3] = tf32bits(oddl ? w1 : w0);
            }
            #pragma unroll
            for (int nt = 0; nt < 8; nt++) {
                uint32_t b0 = fbits(Vs[(8 * kt + (lane & 3)) * VSTR + 8 * nt + (lane >> 2)]);
                uint32_t b1 = fbits(Vs[(8 * kt + 4 + (lane & 3)) * VSTR + 8 * nt + (lane >> 2)]);
                mma8(o[0][nt], A[0], b0, b1);
                mma8(o[1][nt], A[1], b0, b1);
            }
        }
    }

    // Epilogue: normalize + head-major scatter
    const int head = n >> 3, b = n & 7;
    #pragma unroll
    for (int mt = 0; mt < 2; mt++) {
        #pragma unroll
        for (int rh = 0; rh < 2; rh++) {
            const int q = q0 + warp * 32 + mt * 16 + (lane >> 2) + 8 * rh;
            const float inv = 1.0f / lrow[mt * 2 + rh];
            float* orow = out + ((size_t)(b * SEQ + q)) * DMODEL + head * HD;
            #pragma unroll
            for (int nt = 0; nt < 8; nt++) {
                const int cc = 8 * nt + 2 * (lane & 3);
                float2 v = make_float2(o[mt][nt][2 * rh] * inv, o[mt][nt][2 * rh + 1] * inv);
                *(float2*)(orow + cc) = v;
            }
        }
    }
}

extern "C" void kernel_launch(void* const* d_in, const int* in_sizes, int n_in,
                              void* d_out, int out_size)
{
    const float* q_in = (const float*)d_in[0];
    const float* k_in = (const float*)d_in[1];
    const float* v_in = (const float*)d_in[2];
    const float* Wq   = (const float*)d_in[3];
    const float* bq   = (const float*)d_in[4];
    const float* Wk   = (const float*)d_in[5];
    const float* bk   = (const float*)d_in[6];
    const float* Wv   = (const float*)d_in[7];
    const float* bv   = (const float*)d_in[8];
    float* out = (float*)d_out;

    dim3 gp(DMODEL / 128, (BATCH * SEQ) / 128, 3);   // (4, 64, 3)
    proj_kernel<<<gp, 128>>>(q_in, k_in, v_in, Wq, Wk, Wv, bq, bk, bv);

    const int smem_attn = (128 * QSTR + 64 * KSTR + 64 * VSTR) * 4;  // 70656 B
    cudaFuncSetAttribute(attn_kernel, cudaFuncAttributeMaxDynamicSharedMemorySize, smem_attn);
    dim3 ga(SEQ / 128, NB);                          // (8, 64)
    attn_kernel<<<ga, 128, smem_attn>>>(out);
}

// round 4
// speedup vs baseline: 3.3599x; 1.1587x over previous
#include <cuda_runtime.h>
#include <cstdint>

// Problem constants
#define HEADS 8
#define BATCH 8
#define SEQ   1024          // 32*32
#define HD    64
#define DMODEL 512
#define CIN   512
#define NB    (HEADS*BATCH) // 64 head-batches
#define HSTRIDE (BATCH*SEQ*HD) // 524288
#define QSCALE (0.125f * 1.4426950408889634f)   // 1/sqrt(64) * log2(e)

// Scratch (all values tf32-rounded by proj epilogue):
// g_Q: [n][s][pc(hd)]   (pre-scaled by QSCALE)
// g_K: [n][s][pc(hd)]
// g_V: [n][hd][ps(s)]   (transposed per head-batch)
// pc/ps interleave pairs (x, x+4) within groups of 8: x -> (x&~7)|((x&3)<<1)|((x>>2)&1)
__device__ float g_Q[NB * SEQ * HD];
__device__ float g_K[NB * SEQ * HD];
__device__ float g_V[NB * SEQ * HD];

// ---- helpers -------------------------------------------------------------
__device__ __forceinline__ uint32_t tf32bits(float x) {
    uint32_t u; asm("cvt.rna.tf32.f32 %0, %1;" : "=r"(u) : "f"(x)); return u;
}
__device__ __forceinline__ float tf32f(float x) {
    return __uint_as_float(tf32bits(x));
}
__device__ __forceinline__ float ex2(float x) {
    float r; asm("ex2.approx.ftz.f32 %0, %1;" : "=f"(r) : "f"(x)); return r;
}
__device__ __forceinline__ void mma8(float* d, const uint32_t* a, uint32_t b0, uint32_t b1) {
    asm volatile(
        "mma.sync.aligned.m16n8k8.row.col.f32.tf32.tf32.f32 "
        "{%0,%1,%2,%3}, {%4,%5,%6,%7}, {%8,%9}, {%0,%1,%2,%3};\n"
        : "+f"(d[0]), "+f"(d[1]), "+f"(d[2]), "+f"(d[3])
        : "r"(a[0]), "r"(a[1]), "r"(a[2]), "r"(a[3]), "r"(b0), "r"(b1));
}
__device__ __forceinline__ uint32_t fbits(float x) { return __float_as_uint(x); }
__device__ __forceinline__ void cpa16(uint32_t dst, const void* src) {
    asm volatile("cp.async.ca.shared.global [%0], [%1], 16;\n" :: "r"(dst), "l"(src));
}

// ---------------------------------------------------------------------------
// Kernel A: fused Q/K/V projection GEMM, tf32 MMA (R3 mainloop).
// Epilogue writes the conditioned layouts described above.
// ---------------------------------------------------------------------------
#define ASTR 36
#define BSTR 136
__global__ void __launch_bounds__(128, 2) proj_kernel(
    const float* __restrict__ Xq, const float* __restrict__ Xk, const float* __restrict__ Xv,
    const float* __restrict__ Wq, const float* __restrict__ Wk, const float* __restrict__ Wv,
    const float* __restrict__ bq, const float* __restrict__ bk, const float* __restrict__ bv)
{
    __shared__ float As[128 * ASTR];
    __shared__ float Bs[32 * BSTR];

    const int z = blockIdx.z;
    const float* __restrict__ X    = (z == 0) ? Xq : (z == 1) ? Xk : Xv;
    const float* __restrict__ W    = (z == 0) ? Wq : (z == 1) ? Wk : Wv;
    const float* __restrict__ bias = (z == 0) ? bq : (z == 1) ? bk : bv;
    float* __restrict__ Out        = (z == 0) ? g_Q : (z == 1) ? g_K : g_V;

    const int m0 = blockIdx.y * 128;
    const int n0 = blockIdx.x * 128;
    const int tid = threadIdx.x;
    const int lane = tid & 31, warp = tid >> 5;
    const int wm = (warp & 1) * 64;
    const int wn = (warp >> 1) * 64;

    float c[4][8][4];
    #pragma unroll
    for (int mt = 0; mt < 4; mt++)
        #pragma unroll
        for (int nt = 0; nt < 8; nt++)
            #pragma unroll
            for (int i = 0; i < 4; i++) c[mt][nt][i] = 0.0f;

    for (int k0 = 0; k0 < CIN; k0 += 32) {
        __syncthreads();
        {
            const float* src = X + (size_t)(m0 + tid) * CIN + k0;
            float* dst = As + tid * ASTR;
            #pragma unroll
            for (int j = 0; j < 8; j++) {
                float4 v = *(const float4*)(src + 4 * j);
                *(float4*)(dst + 4 * j) =
                    make_float4(tf32f(v.x), tf32f(v.y), tf32f(v.z), tf32f(v.w));
            }
        }
        {
            const float* src = W + (size_t)(k0 + (tid >> 2)) * DMODEL + n0 + (tid & 3) * 4;
            float* dst = Bs + (tid >> 2) * BSTR + (tid & 3) * 4;
            #pragma unroll
            for (int j = 0; j < 8; j++) {
                float4 v = *(const float4*)(src + 16 * j);
                *(float4*)(dst + 16 * j) =
                    make_float4(tf32f(v.x), tf32f(v.y), tf32f(v.z), tf32f(v.w));
            }
        }
        __syncthreads();

        #pragma unroll
        for (int ks = 0; ks < 4; ks++) {
            uint32_t A[4][4];
            #pragma unroll
            for (int mt = 0; mt < 4; mt++) {
                const float* ap = As + (wm + mt * 16 + (lane >> 2)) * ASTR + 8 * ks + (lane & 3);
                A[mt][0] = fbits(ap[0]);
                A[mt][2] = fbits(ap[4]);
                A[mt][1] = fbits(ap[8 * ASTR]);
                A[mt][3] = fbits(ap[8 * ASTR + 4]);
            }
            #pragma unroll
            for (int nt = 0; nt < 8; nt++) {
                uint32_t b0 = fbits(Bs[(8 * ks + (lane & 3)) * BSTR + wn + 8 * nt + (lane >> 2)]);
                uint32_t b1 = fbits(Bs[(8 * ks + 4 + (lane & 3)) * BSTR + wn + 8 * nt + (lane >> 2)]);
                #pragma unroll
                for (int mt = 0; mt < 4; mt++) mma8(c[mt][nt], A[mt], b0, b1);
            }
        }
    }

    // Epilogue: bias + tf32 round + conditioned layout scatter
    #pragma unroll
    for (int mt = 0; mt < 4; mt++) {
        #pragma unroll
        for (int nt = 0; nt < 8; nt++) {
            const int d = n0 + wn + 8 * nt + 2 * (lane & 3);
            const float2 bb = *(const float2*)&bias[d];
            const int head = d >> 6;
            const int dh = d & 63;
            const int p0 = (dh & ~7) | ((dh & 3) << 1) | ((dh >> 2) & 1);
            const int dh1 = dh + 1;
            const int p1 = (dh1 & ~7) | ((dh1 & 3) << 1) | ((dh1 >> 2) & 1);
            #pragma unroll
            for (int rh = 0; rh < 2; rh++) {
                const int m = m0 + wm + 16 * mt + (lane >> 2) + 8 * rh;
                float v0 = c[mt][nt][2 * rh] + bb.x;
                float v1 = c[mt][nt][2 * rh + 1] + bb.y;
                if (z == 0) { v0 = tf32f(v0 * QSCALE); v1 = tf32f(v1 * QSCALE); }
                else        { v0 = tf32f(v0);          v1 = tf32f(v1); }
                if (z == 2) {
                    const int b = m >> 10, s = m & 1023;
                    const int ps = (s & ~7) | ((s & 3) << 1) | ((s >> 2) & 1);
                    float* base = Out + (size_t)head * HSTRIDE + (size_t)b * (SEQ * HD) + ps;
                    base[(size_t)dh * SEQ]  = v0;
                    base[(size_t)dh1 * SEQ] = v1;
                } else {
                    float* base = Out + (size_t)head * HSTRIDE + (size_t)m * HD;
                    base[p0] = v0;
                    base[p1] = v1;
                }
            }
        }
    }
}

// ---------------------------------------------------------------------------
// Kernel B: flash attention, tf32 MMA.
// Block 128 thr / 4 warps, 128 queries (warp: 32 q, mt=2).
// Q fragments live in registers (loaded once). 32-key KV tiles,
// double-buffered via cp.async. K smem [32][72], V smem [64][40] (pair-
// interleaved layouts -> all fragment reads are single LDS.64, conflict-free).
// grid = (8, 64).
// ---------------------------------------------------------------------------
#define KSTR 72
#define VSTR 40

__global__ void __launch_bounds__(128, 2) attn_kernel(float* __restrict__ out)
{
    __shared__ float Ks[2][32 * KSTR];
    __shared__ float Vs[2][64 * VSTR];

    const int n = blockIdx.y;
    const int tid = threadIdx.x;
    const int lane = tid & 31, warp = tid >> 5;
    const int q0 = blockIdx.x * 128;

    const float* Kg = g_K + (size_t)n * SEQ * HD;
    const float* Vg = g_V + (size_t)n * SEQ * HD;   // [64][1024]

    // ---- Q fragments in registers (one-time, from L2-resident g_Q) ----
    uint32_t qA[2][8][4];
    {
        const float* Qg = g_Q + ((size_t)n * SEQ + q0 + warp * 32) * HD;
        #pragma unroll
        for (int mt = 0; mt < 2; mt++)
            #pragma unroll
            for (int ks = 0; ks < 8; ks++) {
                const float* p = Qg + (size_t)(mt * 16 + (lane >> 2)) * HD + 8 * ks + 2 * (lane & 3);
                float2 lo = *(const float2*)p;
                float2 hi = *(const float2*)(p + 8 * HD);
                qA[mt][ks][0] = fbits(lo.x); qA[mt][ks][2] = fbits(lo.y);
                qA[mt][ks][1] = fbits(hi.x); qA[mt][ks][3] = fbits(hi.y);
            }
    }

    float o[2][8][4];
    #pragma unroll
    for (int mt = 0; mt < 2; mt++)
        #pragma unroll
        for (int nt = 0; nt < 8; nt++)
            #pragma unroll
            for (int i = 0; i < 4; i++) o[mt][nt][i] = 0.0f;
    float mrow[4] = {-1e30f, -1e30f, -1e30f, -1e30f};
    float lrow[4] = {0.0f, 0.0f, 0.0f, 0.0f};

    // cp.async staging mappings
    const int krow = tid >> 2, kcol = (tid & 3) * 16;   // 32 rows x 64 floats
    const int vrow = tid >> 1, vcol = (tid & 1) * 16;   // 64 rows x 32 floats
    const uint32_t ks_a = (uint32_t)__cvta_generic_to_shared(&Ks[0][0]);
    const uint32_t vs_a = (uint32_t)__cvta_generic_to_shared(&Vs[0][0]);

    #define ISSUE_TILE(kv, b) do {                                             \
        uint32_t kd = ks_a + (uint32_t)(((b) * 32 * KSTR + krow * KSTR + kcol) * 4); \
        const float* ksrc = Kg + (size_t)((kv) + krow) * HD + kcol;            \
        _Pragma("unroll")                                                      \
        for (int j = 0; j < 4; j++) cpa16(kd + j * 16, ksrc + j * 4);          \
        uint32_t vd = vs_a + (uint32_t)(((b) * 64 * VSTR + vrow * VSTR + vcol) * 4); \
        const float* vsrc = Vg + (size_t)vrow * SEQ + (kv) + vcol;             \
        _Pragma("unroll")                                                      \
        for (int j = 0; j < 4; j++) cpa16(vd + j * 16, vsrc + j * 4);          \
        asm volatile("cp.async.commit_group;\n" ::: "memory");                 \
    } while (0)

    ISSUE_TILE(0, 0);

    const int src0 = (lane & ~3) | ((lane >> 1) & 1);
    const int src2 = src0 | 2;
    const bool oddl = (lane & 1);

    for (int t = 0; t < 32; t++) {
        if (t + 1 < 32) {
            ISSUE_TILE((t + 1) * 32, (t + 1) & 1);
            asm volatile("cp.async.wait_group 1;\n" ::: "memory");
        } else {
            asm volatile("cp.async.wait_group 0;\n" ::: "memory");
        }
        __syncthreads();
        const float* Kb = &Ks[t & 1][0];
        const float* Vb = &Vs[t & 1][0];

        // ---- S = Q * K^T (32 keys) ----
        float s[2][4][4];
        #pragma unroll
        for (int mt = 0; mt < 2; mt++)
            #pragma unroll
            for (int nt = 0; nt < 4; nt++)
                #pragma unroll
                for (int i = 0; i < 4; i++) s[mt][nt][i] = 0.0f;

        #pragma unroll
        for (int ks = 0; ks < 8; ks++) {
            uint32_t b0[4], b1[4];
            #pragma unroll
            for (int nt = 0; nt < 4; nt++) {
                float2 kv2 = *(const float2*)&Kb[(8 * nt + (lane >> 2)) * KSTR + 8 * ks + 2 * (lane & 3)];
                b0[nt] = fbits(kv2.x); b1[nt] = fbits(kv2.y);
            }
            #pragma unroll
            for (int nt = 0; nt < 4; nt++) {
                mma8(s[0][nt], qA[0][ks], b0[nt], b1[nt]);
                mma8(s[1][nt], qA[1][ks], b0[nt], b1[nt]);
            }
        }

        // ---- online softmax (log2 domain) ----
        #pragma unroll
        for (int mt = 0; mt < 2; mt++) {
            #pragma unroll
            for (int rh = 0; rh < 2; rh++) {
                const int sl = mt * 2 + rh, cb = rh * 2;
                float mx = mrow[sl];
                #pragma unroll
                for (int nt = 0; nt < 4; nt++) {
                    mx = fmaxf(mx, s[mt][nt][cb]);
                    mx = fmaxf(mx, s[mt][nt][cb + 1]);
                }
                mx = fmaxf(mx, __shfl_xor_sync(0xffffffffu, mx, 1));
                mx = fmaxf(mx, __shfl_xor_sync(0xffffffffu, mx, 2));
                const float alpha = ex2(mrow[sl] - mx);
                mrow[sl] = mx;
                float sum = 0.0f;
                #pragma unroll
                for (int nt = 0; nt < 4; nt++) {
                    float p0 = ex2(s[mt][nt][cb] - mx);
                    float p1 = ex2(s[mt][nt][cb + 1] - mx);
                    s[mt][nt][cb] = p0; s[mt][nt][cb + 1] = p1;
                    sum += p0 + p1;
                }
                sum += __shfl_xor_sync(0xffffffffu, sum, 1);
                sum += __shfl_xor_sync(0xffffffffu, sum, 2);
                lrow[sl] = lrow[sl] * alpha + sum;
                #pragma unroll
                for (int nt = 0; nt < 8; nt++) {
                    o[mt][nt][cb]     *= alpha;
                    o[mt][nt][cb + 1] *= alpha;
                }
            }
        }

        // ---- O += P * V ----
        #pragma unroll
        for (int kt = 0; kt < 4; kt++) {
            uint32_t A[2][4];
            #pragma unroll
            for (int mt = 0; mt < 2; mt++) {
                float v0 = __shfl_sync(0xffffffffu, s[mt][kt][0], src0);
                float v1 = __shfl_sync(0xffffffffu, s[mt][kt][1], src0);
                float w0 = __shfl_sync(0xffffffffu, s[mt][kt][0], src2);
                float w1 = __shfl_sync(0xffffffffu, s[mt][kt][1], src2);
                A[mt][0] = tf32bits(oddl ? v1 : v0);
                A[mt][2] = tf32bits(oddl ? w1 : w0);
                v0 = __shfl_sync(0xffffffffu, s[mt][kt][2], src0);
                v1 = __shfl_sync(0xffffffffu, s[mt][kt][3], src0);
                w0 = __shfl_sync(0xffffffffu, s[mt][kt][2], src2);
                w1 = __shfl_sync(0xffffffffu, s[mt][kt][3], src2);
                A[mt][1] = tf32bits(oddl ? v1 : v0);
                A[mt][3] = tf32bits(oddl ? w1 : w0);
            }
            #pragma unroll
            for (int nt = 0; nt < 8; nt++) {
                float2 vv = *(const float2*)&Vb[(8 * nt + (lane >> 2)) * VSTR + 8 * kt + 2 * (lane & 3)];
                uint32_t b0 = fbits(vv.x), b1 = fbits(vv.y);
                mma8(o[0][nt], A[0], b0, b1);
                mma8(o[1][nt], A[1], b0, b1);
            }
        }
        __syncthreads();
    }
    #undef ISSUE_TILE

    // Epilogue: normalize + head-major scatter
    const int head = n >> 3, b = n & 7;
    #pragma unroll
    for (int mt = 0; mt < 2; mt++) {
        #pragma unroll
        for (int rh = 0; rh < 2; rh++) {
            const int q = q0 + warp * 32 + mt * 16 + (lane >> 2) + 8 * rh;
            const float inv = 1.0f / lrow[mt * 2 + rh];
            float* orow = out + ((size_t)(b * SEQ + q)) * DMODEL + head * HD;
            #pragma unroll
            for (int nt = 0; nt < 8; nt++) {
                const int cc = 8 * nt + 2 * (lane & 3);
                *(float2*)(orow + cc) =
                    make_float2(o[mt][nt][2 * rh] * inv, o[mt][nt][2 * rh + 1] * inv);
            }
        }
    }
}

extern "C" void kernel_launch(void* const* d_in, const int* in_sizes, int n_in,
                              void* d_out, int out_size)
{
    const float* q_in = (const float*)d_in[0];
    const float* k_in = (const float*)d_in[1];
    const float* v_in = (const float*)d_in[2];
    const float* Wq   = (const float*)d_in[3];
    const float* bq   = (const float*)d_in[4];
    const float* Wk   = (const float*)d_in[5];
    const float* bk   = (const float*)d_in[6];
    const float* Wv   = (const float*)d_in[7];
    const float* bv   = (const float*)d_in[8];
    float* out = (float*)d_out;

    dim3 gp(DMODEL / 128, (BATCH * SEQ) / 128, 3);   // (4, 64, 3)
    proj_kernel<<<gp, 128>>>(q_in, k_in, v_in, Wq, Wk, Wv, bq, bk, bv);

    dim3 ga(SEQ / 128, NB);                          // (8, 64)
    attn_kernel<<<ga, 128>>>(out);
}